// round 14
// baseline (speedup 1.0000x reference)
#include <cuda_runtime.h>
#include <math.h>

#define N_ENT 30000
#define ALL_REL 221
#define D 32
#define EVAL_REL 86
#define B 16
#define E_EDGES 120000
#define BD 512            /* B*D */
#define NBLK 128
#define NTHR 256
#define BM_WORDS 938      /* ceil(N_ENT/32) */
#define NCHUNK (E_EDGES / 32)   /* 3750 warp-chunks, exact */

// ---------- device scratch (zero-init at load; marks/slots restored by cleanup) ----------
// row banks: 0=p0L0, 1=p1L0, 2=p0L1, 3=p1L1. Rows claimed compactly from slot 0, zeroed by the
// winner warp BEFORE the slot is published -> live region ~1MB/bank stays L2-resident.
__device__ float    g_rows[4][N_ENT * BD];
__device__ unsigned g_mark[N_ENT];        // bit k = entity claimed in bank k (zero-invariant)
__device__ unsigned g_slot[4][N_ENT];     // 0 = unpublished, else compact slot+1 (zero-invariant)
__device__ int      g_tL[4][N_ENT];       // winner lists; list index == row slot
__device__ int      g_listCnt[4];
__device__ unsigned g_barCount = 0;
__device__ volatile unsigned g_barGen = 0;
__device__ unsigned g_done = 0;

__device__ __forceinline__ void gridBarrier() {
    __threadfence();
    __syncthreads();
    if (threadIdx.x == 0) {
        unsigned gen = g_barGen;
        if (atomicAdd(&g_barCount, 1u) == NBLK - 1u) {
            g_barCount = 0;
            __threadfence();
            g_barGen = gen + 1u;
        } else {
            while (g_barGen == gen) { __nanosleep(32); }
        }
    }
    __syncthreads();
    __threadfence();
}

// Warp-cooperative claim-or-wait: returns the compact slot for (bank k, entity v).
// Winner warp zeroes the row, fences, then publishes. Losers spin on the published slot.
// Called warp-uniformly. Slot indices bounded by winner count <= N_ENT.
__device__ __forceinline__ int claimOrWait(int k, int v, int lane) {
    int sd = -1;
    if (lane == 0) {
        unsigned bit = 1u << k;
        unsigned old = atomicOr(&g_mark[v], bit);
        if (!(old & bit)) {
            sd = atomicAdd(&g_listCnt[k], 1);
            g_tL[k][sd] = v;
        }
    }
    sd = __shfl_sync(0xffffffffu, sd, 0);
    if (sd >= 0) {                       // winner warp: zero row, publish
        float4* row = (float4*)(g_rows[k] + (size_t)sd * BD);
        #pragma unroll
        for (int j = lane; j < BD / 4; j += 32) row[j] = make_float4(0.f, 0.f, 0.f, 0.f);
        __syncwarp();
        __threadfence();
        if (lane == 0) atomicExch(&g_slot[k][v], (unsigned)(sd + 1));
    } else {                             // loser warp: wait for publication
        if (lane == 0) {
            unsigned s;
            while ((s = *(volatile unsigned*)&g_slot[k][v]) == 0u) { __nanosleep(20); }
            sd = (int)s - 1;
        }
        sd = __shfl_sync(0xffffffffu, sd, 0);
        __threadfence();                 // acquire: row zeroing visible before our atomics
    }
    return sd;
}

__global__ void __launch_bounds__(NTHR, 1)
emer_persist(const int* __restrict__ head, const int* __restrict__ tail,
             const int* __restrict__ eh, const int* __restrict__ et,
             const int* __restrict__ er, const float* __restrict__ ew,
             const float* __restrict__ ent_emb, const float* __restrict__ rel_embs,
             const float* __restrict__ Wlin, const float* __restrict__ blin,
             const float* __restrict__ Wrel, const float* __restrict__ brel,
             const float* __restrict__ Watt, const float* __restrict__ batt,
             const float* __restrict__ Wr, const float* __restrict__ br,
             float* __restrict__ out) {
    const int tid  = threadIdx.x;
    const int bid  = blockIdx.x;
    const int lane = tid & 31;
    const int gw   = (bid * NTHR + tid) >> 5;   // global warp
    const int nw   = (NBLK * NTHR) >> 5;        // 1024 warps

    __shared__ float sRelw[2 * B * ALL_REL];    // 28.3KB, both layers, block-local
    __shared__ float sA[4096];                  // 16KB union: relw tmp | bitmap | conc+staging
    __shared__ float sW[D * D];                 // 4KB
    __shared__ float sBias[D];
    __shared__ int   sHead[B], sTail[B];

    if (tid < 2 * B) {
        int v = (tid < B) ? head[tid] : tail[tid - B];
        if (tid < B) sHead[tid] = v; else sTail[tid - B] = v;
    }
    __syncthreads();

    // ---------------- local relw (both layers, every block; removes cross-block dep) ----------
    {
        float* sHt = sA;             // B*2D = 1024 floats
        float* sH5 = sA + 1024;      // B*5
        for (int idx = tid; idx < B * 2 * D; idx += NTHR) {
            int b = idx / (2 * D), j = idx % (2 * D);
            int ent = (j < D) ? sHead[b] : sTail[b];
            int jj  = (j < D) ? j : j - D;
            sHt[b * 2 * D + j] = ent_emb[ent * D + jj];
        }
        __syncthreads();
        for (int l = 0; l < 2; l++) {
            for (int idx = tid; idx < B * 5; idx += NTHR) {
                int b = idx / 5, k = idx % 5;
                float s = brel[l * 5 + k];
                #pragma unroll 8
                for (int j = 0; j < 2 * D; j++)
                    s += sHt[b * 2 * D + j] * Wrel[l * (2 * D * 5) + j * 5 + k];
                sH5[b * 5 + k] = fmaxf(s, 0.f);
            }
            __syncthreads();
            for (int idx = tid; idx < B * ALL_REL; idx += NTHR) {
                int b = idx / ALL_REL, r = idx % ALL_REL;
                float s = batt[l * ALL_REL + r];
                #pragma unroll
                for (int k = 0; k < 5; k++)
                    s += sH5[b * 5 + k] * Watt[l * (5 * ALL_REL) + k * ALL_REL + r];
                sRelw[l * B * ALL_REL + b * ALL_REL + r] = 1.f / (1.f + expf(-s));
            }
            __syncthreads();
        }
    }

    // ---------------- L0 frontier bitmap (block-local, reuses sA) ----------------
    unsigned* bm = (unsigned*)sA;
    for (int i = tid; i < BM_WORDS; i += NTHR) bm[i] = 0u;
    __syncthreads();
    if (tid < 2 * B) {
        int v = (tid < B) ? sHead[tid] : sTail[tid - B];
        atomicOr(&bm[v >> 5], 1u << (v & 31));
    }
    __syncthreads();

    // ============ Phase A: fused scan + claim + scatter L0 (all blocks, warp-chunked) ==========
    {
        const float* rel0 = rel_embs;
        for (int chunk = gw; chunk < NCHUNK; chunk += nw) {
            int i = chunk * 32 + lane;
            int h = eh[i];
            bool a0 = false, a1 = false;
            if ((bm[h >> 5] >> (h & 31)) & 1u) {
                #pragma unroll
                for (int b = 0; b < B; b++) { a0 |= (h == sHead[b]); a1 |= (h == sTail[b]); }
            }
            int tv = 0, r = 0; float wt = 0.f;
            if (a0 | a1) { tv = et[i]; r = er[i]; wt = ew[i]; }
            unsigned m0 = __ballot_sync(0xffffffffu, a0);
            unsigned m1 = __ballot_sync(0xffffffffu, a1);
            #pragma unroll 1
            for (int p = 0; p < 2; p++) {
                unsigned m = p ? m1 : m0;
                const int* init = p ? sTail : sHead;
                const float* rw = sRelw;   // layer 0
                while (m) {
                    int ln = __ffs(m) - 1; m &= m - 1;
                    int he = __shfl_sync(0xffffffffu, h, ln);
                    int te = __shfl_sync(0xffffffffu, tv, ln);
                    int re = __shfl_sync(0xffffffffu, r, ln);
                    float we = __shfl_sync(0xffffffffu, wt, ln);
                    int sd = claimOrWait(p, te, lane);
                    if (sd < 0) continue;                         // defensive
                    float* drow = g_rows[p] + (size_t)sd * BD;
                    float relv = rel0[re * D + lane] * we * ent_emb[he * D + lane];
                    #pragma unroll
                    for (int b = 0; b < B; b++) {
                        if (init[b] == he)
                            atomicAdd(&drow[b * D + lane], rw[b * ALL_REL + re] * relv);
                    }
                }
            }
        }
    }
    gridBarrier();

    // ==== Phase B: fused scan + claim + scatter L1 with on-the-fly linear-L0 transform =========
    {
        for (int i = tid; i < D * D; i += NTHR) sW[i] = Wlin[i];      // layer-0 weights
        if (tid < D) sBias[tid] = blin[tid];
        __syncthreads();
        const float* rel1 = rel_embs + ALL_REL * D;
        for (int chunk = gw; chunk < NCHUNK; chunk += nw) {
            int i = chunk * 32 + lane;
            int h = eh[i];
            unsigned f = g_mark[h] & 3u;       // L0 frontier bits, finalized in phase A
            int tv = 0, r = 0; float wt = 0.f;
            if (f) { tv = et[i]; r = er[i]; wt = ew[i]; }
            unsigned m0 = __ballot_sync(0xffffffffu, f & 1u);
            unsigned m1 = __ballot_sync(0xffffffffu, f & 2u);
            #pragma unroll 1
            for (int p = 0; p < 2; p++) {
                unsigned m = p ? m1 : m0;
                const float* rw = sRelw + B * ALL_REL;   // layer 1
                while (m) {
                    int ln = __ffs(m) - 1; m &= m - 1;
                    int he = __shfl_sync(0xffffffffu, h, ln);
                    int te = __shfl_sync(0xffffffffu, tv, ln);
                    int re = __shfl_sync(0xffffffffu, r, ln);
                    float we = __shfl_sync(0xffffffffu, wt, ln);
                    int ss = (int)g_slot[p][he] - 1;              // published in phase A
                    int sd = claimOrWait(2 + p, te, lane);
                    if ((ss | sd) < 0) continue;                  // defensive
                    const float* srow = g_rows[p]     + (size_t)ss * BD;  // RAW L0 row
                    float*       drow = g_rows[2 + p] + (size_t)sd * BD;
                    float relv = rel1[re * D + lane] * we;
                    #pragma unroll
                    for (int b = 0; b < B; b++) {
                        float rv = srow[b * D + lane];
                        float acc = sBias[lane];
                        #pragma unroll
                        for (int j = 0; j < D; j++)
                            acc += __shfl_sync(0xffffffffu, rv, j) * sW[j * D + lane];
                        float t = fmaxf(acc, 0.f);                // linear-L0 on demand
                        atomicAdd(&drow[b * D + lane], rw[b * ALL_REL + re] * relv * t);
                    }
                }
            }
        }
    }
    gridBarrier();

    // ====== Phase C: final (b0..7; folds linear-L1)  ||  mark/slot cleanup (b8..127) ===========
    if (bid < 8) {
        float (*conc)[4 * D] = (float (*)[4 * D])sA;   // 2048 floats
        float* st = sA + 2048;                          // 1024 floats raw staging
        for (int i = tid; i < D * D; i += NTHR) sW[i] = Wlin[D * D + i];  // layer-1 weights
        if (tid < D) sBias[tid] = blin[D + tid];
        for (int i = tid; i < BD; i += NTHR) {
            int b = i >> 5, j = i & 31;
            int s3 = (int)g_slot[3][sHead[b]];
            int s2 = (int)g_slot[2][sTail[b]];
            st[i]      = s3 ? g_rows[3][(size_t)(s3 - 1) * BD + b * D + j] : 0.f;
            st[BD + i] = s2 ? g_rows[2][(size_t)(s2 - 1) * BD + b * D + j] : 0.f;
        }
        __syncthreads();
        for (int i = tid; i < B * D; i += NTHR) {
            int b = i >> 5, j = i & 31;
            conc[b][j]     = ent_emb[sHead[b] * D + j];
            conc[b][D + j] = ent_emb[sTail[b] * D + j];
            float a3 = sBias[j], a2 = sBias[j];
            #pragma unroll
            for (int jp = 0; jp < D; jp++) {
                a3 += st[b * D + jp]      * sW[jp * D + j];
                a2 += st[BD + b * D + jp] * sW[jp * D + j];
            }
            conc[b][2 * D + j] = fmaxf(a3, 0.f);   // head_hid = relu(raw3 @ W1 + b1)
            conc[b][3 * D + j] = fmaxf(a2, 0.f);   // tail_hid = relu(raw2 @ W1 + b1)
        }
        __syncthreads();
        int i = bid * NTHR + tid;            // 2048 >= 1376 outputs
        if (i < B * EVAL_REL) {
            int b = i / EVAL_REL, r = i % EVAL_REL;
            float s = br[r];
            #pragma unroll 4
            for (int k = 0; k < 4 * D; k++) s += conc[b][k] * Wr[k * EVAL_REL + r];
            out[b * EVAL_REL + r] = s;
        }
    } else {
        // restore zero-invariance of marks + slots via winner lists (rows zeroed at claim time).
        // Banks 2/3 slots of head/tail entities are still read by final blocks -> last-block-out.
        int c0 = g_listCnt[0], c1 = g_listCnt[1], c2 = g_listCnt[2], c3 = g_listCnt[3];
        int tot = c0 + c1 + c2 + c3;
        int base = (bid - 8) * NTHR + tid;
        int stride = (NBLK - 8) * NTHR;
        for (int idx = base; idx < tot; idx += stride) {
            int i = idx, k, s;
            if (i < c0) { k = 0; s = i; }
            else { i -= c0;
                if (i < c1) { k = 1; s = i; }
                else { i -= c1;
                    if (i < c2) { k = 2; s = i; } else { k = 3; s = i - c2; } } }
            int v = g_tL[k][s];
            g_mark[v] = 0u;                  // idempotent superset clear across lists
            if (k < 2) {
                g_slot[k][v] = 0u;
            } else {
                bool ht = false;
                #pragma unroll
                for (int b = 0; b < B; b++) ht |= (v == sHead[b]) | (v == sTail[b]);
                if (!ht) g_slot[k][v] = 0u;
            }
        }
    }

    // last block out: counters + head/tail bank-2/3 slot clears (final readers done by then)
    __threadfence();
    __syncthreads();
    if (tid == 0) {
        if (atomicAdd(&g_done, 1u) == NBLK - 1u) {
            #pragma unroll
            for (int k = 0; k < 4; k++) g_listCnt[k] = 0;
            #pragma unroll
            for (int b = 0; b < B; b++) {
                g_slot[2][sHead[b]] = 0u; g_slot[2][sTail[b]] = 0u;
                g_slot[3][sHead[b]] = 0u; g_slot[3][sTail[b]] = 0u;
            }
            g_done = 0;
            __threadfence();
        }
    }
}

// ---------------- launch ----------------
extern "C" void kernel_launch(void* const* d_in, const int* in_sizes, int n_in,
                              void* d_out, int out_size) {
    (void)in_sizes; (void)n_in; (void)out_size;
    const int*   head    = (const int*)d_in[0];
    const int*   tail    = (const int*)d_in[1];
    const int*   eh      = (const int*)d_in[2];
    const int*   et      = (const int*)d_in[3];
    const int*   er      = (const int*)d_in[4];
    const float* ew      = (const float*)d_in[5];
    const float* ent_emb = (const float*)d_in[6];
    const float* rel_embs= (const float*)d_in[7];
    const float* Wlin    = (const float*)d_in[8];
    const float* blin    = (const float*)d_in[9];
    const float* Wrel    = (const float*)d_in[10];
    const float* brel    = (const float*)d_in[11];
    const float* Watt    = (const float*)d_in[12];
    const float* batt    = (const float*)d_in[13];
    const float* Wr      = (const float*)d_in[14];
    const float* br      = (const float*)d_in[15];
    float* out = (float*)d_out;

    emer_persist<<<NBLK, NTHR>>>(head, tail, eh, et, er, ew, ent_emb, rel_embs,
                                 Wlin, blin, Wrel, brel, Watt, batt, Wr, br, out);
}

// round 16
// speedup vs baseline: 1.7059x; 1.7059x over previous
#include <cuda_runtime.h>
#include <math.h>

#define N_ENT 30000
#define ALL_REL 221
#define D 32
#define EVAL_REL 86
#define B 16
#define E_EDGES 120000
#define BD 512            /* B*D */
#define NBLK 128
#define NTHR 256
#define BM_WORDS 938      /* ceil(N_ENT/32) */

// ---------- device scratch (zero-initialized at load; marks/slots restored by cleanup) ----------
// row banks: 0=p0L0, 1=p1L0, 2=p0L1, 3=p1L1. Rows claimed compactly from slot 0, zeroed at claim
// -> live region ~1MB/bank stays L2-resident; rows need NOT be zero between replays.
__device__ float    g_rows[4][N_ENT * BD];
__device__ unsigned g_mark[N_ENT];        // bit k = entity claimed in bank k (zero-invariant)
__device__ unsigned g_slot[4][N_ENT];     // 0 = none, else compact slot+1 (zero-invariant)
__device__ int      g_eL[4][E_EDGES];     // active edge lists per (pass, layer)
__device__ int      g_tL[4][N_ENT];       // winner lists; list index == row slot
__device__ int      g_listCnt[4];
__device__ int      g_eCnt[4];
__device__ float    g_relw[2 * B * ALL_REL];
__device__ unsigned g_barCount = 0;
__device__ volatile unsigned g_barGen = 0;
__device__ unsigned g_done = 0;

// winner-only compact slot claim: slot index == list position, bounded by N_ENT. No transients.
__device__ __forceinline__ void claim(int k, int v) {
    unsigned bit = 1u << k;
    unsigned old = atomicOr(&g_mark[v], bit);
    if (!(old & bit)) {
        int s = atomicAdd(&g_listCnt[k], 1);
        g_tL[k][s] = v;
        g_slot[k][v] = (unsigned)(s + 1);
        float4* row = (float4*)(g_rows[k] + (size_t)s * BD);
        #pragma unroll 8
        for (int j = 0; j < BD / 4; j++) row[j] = make_float4(0.f, 0.f, 0.f, 0.f);
    }
}

__global__ void __launch_bounds__(NTHR, 1)
emer_persist(const int* __restrict__ head, const int* __restrict__ tail,
             const int* __restrict__ eh, const int* __restrict__ et,
             const int* __restrict__ er, const float* __restrict__ ew,
             const float* __restrict__ ent_emb, const float* __restrict__ rel_embs,
             const float* __restrict__ Wlin, const float* __restrict__ blin,
             const float* __restrict__ Wrel, const float* __restrict__ brel,
             const float* __restrict__ Watt, const float* __restrict__ batt,
             const float* __restrict__ Wr, const float* __restrict__ br,
             float* __restrict__ out) {
    const int tid  = threadIdx.x;
    const int bid  = blockIdx.x;
    const int lane = tid & 31;
    const int gw   = (bid * NTHR + tid) >> 5;   // global warp
    const int nw   = (NBLK * NTHR) >> 5;        // 1024 warps

    __shared__ float sA[4096];            // 16KB union: bitmap | relw tmp | conc+staging
    __shared__ float sRelw[B * ALL_REL];  // 14.1KB (one layer at a time)
    __shared__ float sW[D * D];           // 4KB
    __shared__ float sBias[D];
    __shared__ int   sHead[B], sTail[B];
    __shared__ unsigned sGen;

    // split-phase grid barrier: arrive -> (prefetch) -> wait
    auto barArrive = [&]() {
        __threadfence();
        __syncthreads();
        if (tid == 0) {
            sGen = g_barGen;
            if (atomicAdd(&g_barCount, 1u) == NBLK - 1u) {
                g_barCount = 0;
                __threadfence();
                g_barGen = sGen + 1u;
            }
        }
        __syncthreads();        // sGen visible; all block warps past phase work
    };
    auto barWait = [&]() {
        if (tid == 0) { while (g_barGen == sGen) { __nanosleep(32); } }
        __syncthreads();
        __threadfence();        // acquire: other SMs' writes visible
    };

    if (tid < 2 * B) {
        int v = (tid < B) ? head[tid] : tail[tid - B];
        if (tid < B) sHead[tid] = v; else sTail[tid - B] = v;
    }
    __syncthreads();

    // ================= S0: relw (b0:l0, b1:l1)  ||  scan L0 + claims (b2..127) =================
    if (bid < 2) {
        const int l = bid;
        float* sHt = sA;             // B*2D = 1024 floats
        float* sH5 = sA + 1024;      // B*5
        for (int idx = tid; idx < B * 2 * D; idx += NTHR) {
            int b = idx / (2 * D), j = idx % (2 * D);
            int ent = (j < D) ? sHead[b] : sTail[b];
            int jj  = (j < D) ? j : j - D;
            sHt[b * 2 * D + j] = ent_emb[ent * D + jj];
        }
        __syncthreads();
        for (int idx = tid; idx < B * 5; idx += NTHR) {
            int b = idx / 5, k = idx % 5;
            float s = brel[l * 5 + k];
            #pragma unroll 8
            for (int j = 0; j < 2 * D; j++)
                s += sHt[b * 2 * D + j] * Wrel[l * (2 * D * 5) + j * 5 + k];
            sH5[b * 5 + k] = fmaxf(s, 0.f);
        }
        __syncthreads();
        for (int idx = tid; idx < B * ALL_REL; idx += NTHR) {
            int b = idx / ALL_REL, r = idx % ALL_REL;
            float s = batt[l * ALL_REL + r];
            #pragma unroll
            for (int k = 0; k < 5; k++)
                s += sH5[b * 5 + k] * Watt[l * (5 * ALL_REL) + k * ALL_REL + r];
            g_relw[l * B * ALL_REL + b * ALL_REL + r] = 1.f / (1.f + expf(-s));
        }
    } else {
        unsigned* bm = (unsigned*)sA;
        for (int i = tid; i < BM_WORDS; i += NTHR) bm[i] = 0u;
        __syncthreads();
        if (tid < 2 * B) {
            int v = (tid < B) ? sHead[tid] : sTail[tid - B];
            atomicOr(&bm[v >> 5], 1u << (v & 31));
        }
        __syncthreads();
        const int4* eh4 = (const int4*)eh;
        const int NQ = E_EDGES / 4;
        int base = (bid - 2) * NTHR + tid;
        int stride = (NBLK - 2) * NTHR;
        for (int q = base; q < NQ; q += stride) {
            int4 hv = eh4[q];
            #pragma unroll
            for (int j = 0; j < 4; j++) {
                int h = (j == 0) ? hv.x : (j == 1) ? hv.y : (j == 2) ? hv.z : hv.w;
                if ((bm[h >> 5] >> (h & 31)) & 1u) {
                    bool a0 = false, a1 = false;
                    #pragma unroll
                    for (int b = 0; b < B; b++) { a0 |= (h == sHead[b]); a1 |= (h == sTail[b]); }
                    if (a0 | a1) {
                        int e = 4 * q + j;
                        int tv = et[e];
                        if (a0) { g_eL[0][atomicAdd(&g_eCnt[0], 1)] = e; claim(0, tv); }
                        if (a1) { g_eL[1][atomicAdd(&g_eCnt[1], 1)] = e; claim(1, tv); }
                    }
                }
            }
        }
    }
    barArrive();
    barWait();   // (g_relw only becomes safe here — nothing useful to prefetch pre-wait)

    // ===== S1: scatter L0 (b0..31; src = ent_emb masked)  ||  scan L1 + claims (b32..127) ======
    if (bid < 32) {
        for (int i = tid; i < B * ALL_REL; i += NTHR) sRelw[i] = g_relw[i];
        __syncthreads();
        int n0 = g_eCnt[0], n1 = g_eCnt[1];
        const float* rel0 = rel_embs;
        int w0 = (bid * NTHR + tid) >> 5;
        int nw0 = (32 * NTHR) >> 5;     // 256 warps
        for (int w = w0; w < n0 + n1; w += nw0) {
            int e, p;
            if (w < n0) { e = g_eL[0][w];      p = 0; }
            else        { e = g_eL[1][w - n0]; p = 1; }
            int h = eh[e], tv = et[e], r = er[e];
            int sd = (int)g_slot[p][tv] - 1;
            if (sd < 0) continue;                       // defensive, never taken
            float* drow = g_rows[p] + (size_t)sd * BD;
            float relv = rel0[r * D + lane] * ew[e] * ent_emb[h * D + lane];
            const int* init = p ? sTail : sHead;
            #pragma unroll
            for (int b = 0; b < B; b++) {
                if (init[b] == h)
                    atomicAdd(&drow[b * D + lane], sRelw[b * ALL_REL + r] * relv);
            }
        }
    } else {
        // scan L1: frontier = mark bits 0/1, finalized in S0 (claims here touch bits 2/3 only)
        const int4* eh4 = (const int4*)eh;
        const int NQ = E_EDGES / 4;
        int base = (bid - 32) * NTHR + tid;
        int stride = (NBLK - 32) * NTHR;
        for (int q = base; q < NQ; q += stride) {
            int4 hv = eh4[q];
            #pragma unroll
            for (int j = 0; j < 4; j++) {
                int h = (j == 0) ? hv.x : (j == 1) ? hv.y : (j == 2) ? hv.z : hv.w;
                unsigned f = g_mark[h] & 3u;
                if (f) {
                    int e = 4 * q + j;
                    int tv = et[e];
                    if (f & 1u) { g_eL[2][atomicAdd(&g_eCnt[2], 1)] = e; claim(2, tv); }
                    if (f & 2u) { g_eL[3][atomicAdd(&g_eCnt[3], 1)] = e; claim(3, tv); }
                }
            }
        }
    }
    barArrive();
    // prefetch S2 state while waiting: g_relw synced at barrier-1; Wlin/blin input-constant
    for (int i = tid; i < B * ALL_REL; i += NTHR) sRelw[i] = g_relw[B * ALL_REL + i];
    for (int i = tid; i < D * D; i += NTHR) sW[i] = Wlin[i];          // layer-0 weights
    if (tid < D) sBias[tid] = blin[tid];
    barWait();

    // ====== S2: scatter L1 (all blocks) with ON-THE-FLY linear-L0 transform of source rows ======
    {
        int n2 = g_eCnt[2], n3 = g_eCnt[3];
        const float* rel1 = rel_embs + ALL_REL * D;
        for (int w = gw; w < n2 + n3; w += nw) {
            int e, p;
            if (w < n2) { e = g_eL[2][w];      p = 0; }
            else        { e = g_eL[3][w - n2]; p = 1; }
            int h = eh[e], tv = et[e], r = er[e];
            int ss = (int)g_slot[p][h] - 1;
            int sd = (int)g_slot[2 + p][tv] - 1;
            if ((ss | sd) < 0) continue;                // defensive
            const float* srow = g_rows[p]     + (size_t)ss * BD;   // RAW layer-0 accumulation
            float*       drow = g_rows[2 + p] + (size_t)sd * BD;
            float relv = rel1[r * D + lane] * ew[e];
            #pragma unroll
            for (int b = 0; b < B; b++) {
                float rv = srow[b * D + lane];          // coalesced warp load of raw row slice
                float acc = sBias[lane];
                #pragma unroll
                for (int j = 0; j < D; j++)
                    acc += __shfl_sync(0xffffffffu, rv, j) * sW[j * D + lane];
                float t = fmaxf(acc, 0.f);              // = linear-L0 output, recomputed on demand
                atomicAdd(&drow[b * D + lane], sRelw[b * ALL_REL + r] * relv * t);
            }
        }
    }
    barArrive();
    // prefetch S3 state: layer-1 weights (input-constant)
    for (int i = tid; i < D * D; i += NTHR) sW[i] = Wlin[D * D + i];
    if (tid < D) sBias[tid] = blin[D + tid];
    barWait();

    // ====== S3: final (b0..7; folds linear-L1 into readout)  ||  mark/slot cleanup (b8..127) ====
    if (bid < 8) {
        float (*conc)[4 * D] = (float (*)[4 * D])sA;   // 2048 floats
        float* st = sA + 2048;                          // 1024 floats raw staging
        // stage raw L1 rows: st[0..511] = bank3 @ head (b-slice), st[512..1023] = bank2 @ tail
        for (int i = tid; i < BD; i += NTHR) {
            int b = i >> 5, j = i & 31;
            int s3 = (int)g_slot[3][sHead[b]];
            int s2 = (int)g_slot[2][sTail[b]];
            st[i]      = s3 ? g_rows[3][(size_t)(s3 - 1) * BD + b * D + j] : 0.f;
            st[BD + i] = s2 ? g_rows[2][(size_t)(s2 - 1) * BD + b * D + j] : 0.f;
        }
        __syncthreads();
        for (int i = tid; i < B * D; i += NTHR) {
            int b = i >> 5, j = i & 31;
            conc[b][j]     = ent_emb[sHead[b] * D + j];
            conc[b][D + j] = ent_emb[sTail[b] * D + j];
            float a3 = sBias[j], a2 = sBias[j];
            #pragma unroll
            for (int jp = 0; jp < D; jp++) {
                a3 += st[b * D + jp]      * sW[jp * D + j];
                a2 += st[BD + b * D + jp] * sW[jp * D + j];
            }
            conc[b][2 * D + j] = fmaxf(a3, 0.f);   // head_hid = relu(raw3 @ W1 + b1)
            conc[b][3 * D + j] = fmaxf(a2, 0.f);   // tail_hid = relu(raw2 @ W1 + b1)
        }
        __syncthreads();
        int i = bid * NTHR + tid;            // 2048 >= 1376 outputs
        if (i < B * EVAL_REL) {
            int b = i / EVAL_REL, r = i % EVAL_REL;
            float s = br[r];
            #pragma unroll 4
            for (int k = 0; k < 4 * D; k++) s += conc[b][k] * Wr[k * EVAL_REL + r];
            out[b * EVAL_REL + r] = s;
        }
    } else {
        // restore zero-invariance of marks + slots via winner lists (rows zeroed at claim time).
        // Banks 2/3 slots of head/tail entities still read by final blocks -> last-block-out.
        int c0 = g_listCnt[0], c1 = g_listCnt[1], c2 = g_listCnt[2], c3 = g_listCnt[3];
        int tot = c0 + c1 + c2 + c3;
        int base = (bid - 8) * NTHR + tid;
        int stride = (NBLK - 8) * NTHR;
        for (int idx = base; idx < tot; idx += stride) {
            int i = idx, k, s;
            if (i < c0) { k = 0; s = i; }
            else { i -= c0;
                if (i < c1) { k = 1; s = i; }
                else { i -= c1;
                    if (i < c2) { k = 2; s = i; } else { k = 3; s = i - c2; } } }
            int v = g_tL[k][s];
            g_mark[v] = 0u;                  // idempotent superset clear across lists
            if (k < 2) {
                g_slot[k][v] = 0u;
            } else {
                bool ht = false;
                #pragma unroll
                for (int b = 0; b < B; b++) ht |= (v == sHead[b]) | (v == sTail[b]);
                if (!ht) g_slot[k][v] = 0u;
            }
        }
    }

    // last block out: counters + head/tail bank-2/3 slot clears (final readers done by then)
    __threadfence();
    __syncthreads();
    if (tid == 0) {
        if (atomicAdd(&g_done, 1u) == NBLK - 1u) {
            #pragma unroll
            for (int k = 0; k < 4; k++) { g_listCnt[k] = 0; g_eCnt[k] = 0; }
            #pragma unroll
            for (int b = 0; b < B; b++) {
                g_slot[2][sHead[b]] = 0u; g_slot[2][sTail[b]] = 0u;
                g_slot[3][sHead[b]] = 0u; g_slot[3][sTail[b]] = 0u;
            }
            g_done = 0;
            __threadfence();
        }
    }
}

// ---------------- launch ----------------
extern "C" void kernel_launch(void* const* d_in, const int* in_sizes, int n_in,
                              void* d_out, int out_size) {
    (void)in_sizes; (void)n_in; (void)out_size;
    const int*   head    = (const int*)d_in[0];
    const int*   tail    = (const int*)d_in[1];
    const int*   eh      = (const int*)d_in[2];
    const int*   et      = (const int*)d_in[3];
    const int*   er      = (const int*)d_in[4];
    const float* ew      = (const float*)d_in[5];
    const float* ent_emb = (const float*)d_in[6];
    const float* rel_embs= (const float*)d_in[7];
    const float* Wlin    = (const float*)d_in[8];
    const float* blin    = (const float*)d_in[9];
    const float* Wrel    = (const float*)d_in[10];
    const float* brel    = (const float*)d_in[11];
    const float* Watt    = (const float*)d_in[12];
    const float* batt    = (const float*)d_in[13];
    const float* Wr      = (const float*)d_in[14];
    const float* br      = (const float*)d_in[15];
    float* out = (float*)d_out;

    emer_persist<<<NBLK, NTHR>>>(head, tail, eh, et, er, ew, ent_emb, rel_embs,
                                 Wlin, blin, Wrel, brel, Watt, batt, Wr, br, out);
}